// round 15
// baseline (speedup 1.0000x reference)
#include <cuda_runtime.h>
#include <cuda_fp16.h>
#include <math.h>
#include <stdint.h>

#define B_  2
#define T_  2048
#define C_  2048
#define H_  16
#define HK_ 8
#define D_  128
#define G_  2

// ---------------- scratch ----------------
__device__ __half g_xh[(size_t)B_ * T_ * C_];
__device__ __half g_qkvh[(size_t)B_ * T_ * 4096];
__device__ __half g_atth[(size_t)B_ * T_ * 2048];
__device__ __half g_wth[4096 * 2048 + 2048 * 2048];
__device__ float2 g_tab[T_ * 64];

// ---------------- helpers ----------------
__device__ __forceinline__ uint32_t smem_u32(const void* p) {
    uint32_t a;
    asm("{ .reg .u64 t; cvta.to.shared.u64 t, %1; cvt.u32.u64 %0, t; }" : "=r"(a) : "l"(p));
    return a;
}
__device__ __forceinline__ void cp_async16(uint32_t dst, const void* src) {
    asm volatile("cp.async.cg.shared.global [%0], [%1], 16;" :: "r"(dst), "l"(src));
}
#define CP_COMMIT() asm volatile("cp.async.commit_group;" ::: "memory")
#define CP_WAIT(n)  asm volatile("cp.async.wait_group %0;" :: "n"(n) : "memory")

#define MMA_F16(d, a, b)                                                       \
    asm volatile(                                                              \
        "mma.sync.aligned.m16n8k16.row.col.f32.f16.f16.f32 "                   \
        "{%0,%1,%2,%3}, {%4,%5,%6,%7}, {%8,%9}, {%0,%1,%2,%3};\n"              \
        : "+f"((d)[0]), "+f"((d)[1]), "+f"((d)[2]), "+f"((d)[3])               \
        : "r"((a)[0]), "r"((a)[1]), "r"((a)[2]), "r"((a)[3]),                  \
          "r"((b)[0]), "r"((b)[1]))

#define LDSM_X4(r, addr)                                                       \
    asm volatile("ldmatrix.sync.aligned.m8n8.x4.shared.b16 {%0,%1,%2,%3}, [%4];" \
        : "=r"((r)[0]), "=r"((r)[1]), "=r"((r)[2]), "=r"((r)[3]) : "r"(addr))

__device__ __forceinline__ uint32_t pack_h2(float a, float b) {
    __half2 h = __floats2half2_rn(a, b);
    return *(uint32_t*)&h;
}

// ---------------- fused prep kernel ----------------
__global__ __launch_bounds__(256)
void prep_all(const float* __restrict__ x, const float* __restrict__ Wq,
              const float* __restrict__ Wk, const float* __restrict__ Wv,
              const float* __restrict__ Wo, __half* __restrict__ xh,
              __half* __restrict__ wth, float2* __restrict__ tab) {
    int bid = blockIdx.x;
    if (bid < 12288) {
        __shared__ float tile[32][33];
        const float* W;
        __half* Wt;
        int N, lbid;
        if (bid < 4096)      { W = Wq; Wt = wth;               N = 2048; lbid = bid; }
        else if (bid < 6144) { W = Wk; Wt = wth + 2048 * 2048; N = 1024; lbid = bid - 4096; }
        else if (bid < 8192) { W = Wv; Wt = wth + 3072 * 2048; N = 1024; lbid = bid - 6144; }
        else                 { W = Wo; Wt = wth + 4096 * 2048; N = 2048; lbid = bid - 8192; }
        const int K = 2048;
        int tn = N / 32;
        int n0 = (lbid % tn) * 32, k0 = (lbid / tn) * 32;
        int tx = threadIdx.x & 31, ty = threadIdx.x >> 5;
#pragma unroll
        for (int j = 0; j < 32; j += 8)
            tile[ty + j][tx] = W[(size_t)(k0 + ty + j) * N + n0 + tx];
        __syncthreads();
#pragma unroll
        for (int j = 0; j < 32; j += 8)
            Wt[(size_t)(n0 + ty + j) * K + k0 + tx] = __float2half_rn(tile[tx][ty + j]);
    } else if (bid < 16384) {
        int i = (bid - 12288) * 256 + threadIdx.x;
        float4 v0 = ((const float4*)x)[i * 2];
        float4 v1 = ((const float4*)x)[i * 2 + 1];
        uint4 u;
        u.x = pack_h2(v0.x, v0.y); u.y = pack_h2(v0.z, v0.w);
        u.z = pack_h2(v1.x, v1.y); u.w = pack_h2(v1.z, v1.w);
        ((uint4*)xh)[i] = u;
    } else {
        int i = (bid - 16384) * 256 + threadIdx.x;
        int j = i & 63, t = i >> 6;
        float theta = powf(10000.0f, (float)(2 * j) * (1.0f / 128.0f));
        float freq = (float)t / theta;
        tab[i] = make_float2(cosf(freq), sinf(freq));
    }
}

// -------- 3-stage pipelined fp16 GEMM, 128x128 block, 64x32 warp tiles ------
#define KCH 64
#define HSTR 72
#define STAGEH (2 * 128 * HSTR)
#define GEMM_SMEM_BYTES (3 * STAGEH * 2)

__global__ __launch_bounds__(256, 2)
void gemm_h(const __half* __restrict__ A, const __half* __restrict__ Bt,
            __half* __restrict__ Ch, float* __restrict__ Cf,
            int M, int N, int K, int do_rope, int out_half,
            const float2* __restrict__ tab) {
    extern __shared__ __align__(16) __half smh[];
    const uint32_t sbase = smem_u32(smh);

    const int tid = threadIdx.x;
    const int lane = tid & 31;
    const int wid = tid >> 5;
    const int g = lane >> 2, t = lane & 3;
    const int wm = (wid >> 2) * 64;
    const int wn = (wid & 3) * 32;
    const int m0 = blockIdx.y * 128, n0 = blockIdx.x * 128;

    const __half* Ab = A + (size_t)m0 * K;
    const __half* Bb = Bt + (size_t)n0 * K;

    float acc[4][4][4];
#pragma unroll
    for (int mi = 0; mi < 4; mi++)
#pragma unroll
        for (int ni = 0; ni < 4; ni++)
#pragma unroll
            for (int r = 0; r < 4; r++) acc[mi][ni][r] = 0.f;

    const int nchunk = K / KCH;
    const int r_ld = tid >> 3, c_ld = (tid & 7) * 8;
    const uint32_t ld_off = (uint32_t)((r_ld * HSTR + c_ld) * 2);

    const uint32_t a_lds = (uint32_t)(((wm + (lane & 15)) * HSTR + ((lane & 16) >> 1)) * 2);
    const uint32_t b_lds = (uint32_t)(((wn + (lane & 7) + ((lane & 16) >> 1)) * HSTR + (lane & 8)) * 2);

#pragma unroll
    for (int p = 0; p < 2; p++) {
        uint32_t sa = sbase + (uint32_t)(p * STAGEH * 2) + ld_off;
        const int k0 = p * KCH;
#pragma unroll
        for (int it = 0; it < 4; it++) {
            int r = r_ld + it * 32;
            uint32_t d = sa + (uint32_t)(it * 32 * HSTR * 2);
            cp_async16(d, Ab + (size_t)r * K + k0 + c_ld);
            cp_async16(d + 128 * HSTR * 2, Bb + (size_t)r * K + k0 + c_ld);
        }
        CP_COMMIT();
    }

    for (int c = 0; c < nchunk; c++) {
        if (c + 1 < nchunk) { CP_WAIT(1); } else { CP_WAIT(0); }
        __syncthreads();
        if (c + 2 < nchunk) {
            const int k0 = (c + 2) * KCH;
            uint32_t sa = sbase + (uint32_t)(((c + 2) % 3) * STAGEH * 2) + ld_off;
#pragma unroll
            for (int it = 0; it < 4; it++) {
                int r = r_ld + it * 32;
                uint32_t d = sa + (uint32_t)(it * 32 * HSTR * 2);
                cp_async16(d, Ab + (size_t)r * K + k0 + c_ld);
                cp_async16(d + 128 * HSTR * 2, Bb + (size_t)r * K + k0 + c_ld);
            }
            CP_COMMIT();
        }

        const uint32_t Abase = sbase + (uint32_t)((c % 3) * STAGEH * 2);
        const uint32_t Bbase = Abase + 128 * HSTR * 2;

#pragma unroll
        for (int kk = 0; kk < KCH; kk += 16) {
            uint32_t af[4][4], bf[2][4];
#pragma unroll
            for (int mi = 0; mi < 4; mi++)
                LDSM_X4(af[mi], Abase + a_lds + (uint32_t)((mi * 16 * HSTR + kk) * 2));
#pragma unroll
            for (int nb = 0; nb < 2; nb++)
                LDSM_X4(bf[nb], Bbase + b_lds + (uint32_t)((nb * 16 * HSTR + kk) * 2));
#pragma unroll
            for (int mi = 0; mi < 4; mi++)
#pragma unroll
                for (int ni = 0; ni < 4; ni++)
                    MMA_F16(acc[mi][ni], af[mi], (&bf[ni >> 1][(ni & 1) * 2]));
        }
    }
    __syncthreads();

    float* sC = (float*)smh;
#pragma unroll
    for (int mi = 0; mi < 4; mi++)
#pragma unroll
        for (int ni = 0; ni < 4; ni++) {
            int col = wn + ni * 8 + 2 * t;
            int r0 = wm + mi * 16 + g;
            *(float2*)&sC[r0 * 132 + col] = make_float2(acc[mi][ni][0], acc[mi][ni][1]);
            *(float2*)&sC[(r0 + 8) * 132 + col] = make_float2(acc[mi][ni][2], acc[mi][ni][3]);
        }
    __syncthreads();

    if (do_rope && n0 < 3072) {
#pragma unroll
        for (int it = 0; it < 32; it++) {
            int i = tid + it * 256;
            int r = i >> 6, j = i & 63;
            int tpos = (m0 + r) & (T_ - 1);
            float2 cs = tab[tpos * 64 + j];
            float x1 = sC[r * 132 + j];
            float x2 = sC[r * 132 + j + 64];
            sC[r * 132 + j]      = x1 * cs.x - x2 * cs.y;
            sC[r * 132 + j + 64] = x2 * cs.x + x1 * cs.y;
        }
        __syncthreads();
    }

    if (out_half) {
#pragma unroll
        for (int it = 0; it < 16; it++) {
            int i = tid + it * 256;
            int r = i >> 5, c4 = (i & 31) * 4;
            uint2 u = make_uint2(pack_h2(sC[r * 132 + c4], sC[r * 132 + c4 + 1]),
                                 pack_h2(sC[r * 132 + c4 + 2], sC[r * 132 + c4 + 3]));
            *(uint2*)&Ch[(size_t)(m0 + r) * N + n0 + c4] = u;
        }
    } else {
#pragma unroll
        for (int it = 0; it < 16; it++) {
            int i = tid + it * 256;
            int r = i >> 5, c4 = (i & 31) * 4;
            float4 v = make_float4(sC[r * 132 + c4], sC[r * 132 + c4 + 1],
                                   sC[r * 132 + c4 + 2], sC[r * 132 + c4 + 3]);
            *(float4*)&Cf[(size_t)(m0 + r) * N + n0 + c4] = v;
        }
    }
}

// ------- Flash attention: 2-stage KV (2 syncs/tile), 2 CTAs/SM -------
#define AM 128
#define AN 64
#define QH 136
#define PH 72
#define KVBUF (AN * QH)
// halfs: QP region 128*136=17408 + 4 KV bufs 34816 = 52224 -> 104448 B
#define ATTN_SMEM_BYTES ((AM * QH + 4 * KVBUF) * 2)

__global__ __launch_bounds__(256, 2)
void attn_kernel(const __half* __restrict__ qkv, __half* __restrict__ out) {
    extern __shared__ __align__(16) __half sm[];
    __half* sQ = sm;                    // reused as sP after Q hoist
    __half* sKV = sQ + AM * QH;
    __half* sP = sQ;
    const uint32_t kvbase = smem_u32(sKV);
    const uint32_t qbase = smem_u32(sQ);
    const uint32_t pbase = qbase;

    const int tid = threadIdx.x;
    const int lane = tid & 31;
    const int wid = tid >> 5;
    const int g = lane >> 2, t = lane & 3;
    const int qt = (gridDim.x - 1) - blockIdx.x;
    const int h = blockIdx.y, b = blockIdx.z;
    const int kh = h / G_;
    const int q0 = qt * AM;
    const int wm = wid * 16;
    const float scale = 0.08838834764831845f;

    const int qoff = h * D_;
    const int koff = 2048 + kh * D_;
    const int voff = 3072 + kh * D_;

    const uint32_t q_lds = (uint32_t)(((wm + (lane & 15)) * QH + ((lane & 16) >> 1)) * 2);
    const uint32_t k_lds = (uint32_t)((((lane & 7) + ((lane & 16) >> 1)) * QH + (lane & 8)) * 2);
    const uint32_t p_lds = (uint32_t)(((wm + (lane & 15)) * PH + ((lane & 16) >> 1)) * 2);

    // stage Q -> smem -> register fragments
#pragma unroll
    for (int it = 0; it < 8; it++) {
        int i = tid + it * 256;
        int r = i >> 4, c8 = (i & 15) * 8;
        *(uint4*)&sQ[r * QH + c8] =
            *(const uint4*)&qkv[(size_t)(b * T_ + q0 + r) * 4096 + qoff + c8];
    }
    __syncthreads();
    uint32_t qf[8][4];
#pragma unroll
    for (int kk8 = 0; kk8 < 8; kk8++)
        LDSM_X4(qf[kk8], qbase + q_lds + (uint32_t)(kk8 * 16 * 2));
    __syncthreads();

    float m0 = -1e30f, m1 = -1e30f, l0 = 0.f, l1 = 0.f;
    float o[16][4];
#pragma unroll
    for (int ni = 0; ni < 16; ni++)
#pragma unroll
        for (int r = 0; r < 4; r++) o[ni][r] = 0.f;

    const int qr0 = q0 + wm + g, qr1 = qr0 + 8;
    const int ntiles = 2 * qt + 2;

    // prologue: tile 0 into buffer 0
    {
#pragma unroll
        for (int it = 0; it < 8; it++) {
            int i = tid + it * 256;
            int r = (i >> 4) & 63, c8 = (i & 15) * 8;
            size_t rowb = (size_t)(b * T_ + r) * 4096;
            uint32_t d = kvbase + (uint32_t)((r * QH + c8) * 2);
            if (i < 1024) cp_async16(d, &qkv[rowb + koff + c8]);
            else          cp_async16(d + KVBUF * 2, &qkv[rowb + voff + c8]);
        }
        CP_COMMIT();
    }

    for (int kt = 0; kt < ntiles; kt++) {
        // issue loads for kt+1 (buffer was drained by trailing sync of kt-1)
        if (kt + 1 < ntiles) {
            const int k0n = (kt + 1) * AN;
            uint32_t base = kvbase + (uint32_t)(((kt + 1) & 1) * 2 * KVBUF * 2);
#pragma unroll
            for (int it = 0; it < 8; it++) {
                int i = tid + it * 256;
                int r = (i >> 4) & 63, c8 = (i & 15) * 8;
                size_t rowb = (size_t)(b * T_ + k0n + r) * 4096;
                uint32_t d = base + (uint32_t)((r * QH + c8) * 2);
                if (i < 1024) cp_async16(d, &qkv[rowb + koff + c8]);
                else          cp_async16(d + KVBUF * 2, &qkv[rowb + voff + c8]);
            }
            CP_COMMIT();
            CP_WAIT(1);
        } else {
            CP_WAIT(0);
        }
        __syncthreads();

        const uint32_t Kb = kvbase + (uint32_t)((kt & 1) * 2 * KVBUF * 2);
        const __half* sV = sKV + (kt & 1) * 2 * KVBUF + KVBUF;

        float sacc[8][4];
#pragma unroll
        for (int ni = 0; ni < 8; ni++)
#pragma unroll
            for (int r = 0; r < 4; r++) sacc[ni][r] = 0.f;

#pragma unroll
        for (int kk8 = 0; kk8 < 8; kk8++) {
            uint32_t kf[4][4];
#pragma unroll
            for (int nb = 0; nb < 4; nb++)
                LDSM_X4(kf[nb], Kb + k_lds + (uint32_t)((nb * 16 * QH + kk8 * 16) * 2));
#pragma unroll
            for (int ni = 0; ni < 8; ni++)
                MMA_F16(sacc[ni], qf[kk8], (&kf[ni >> 1][(ni & 1) * 2]));
        }

        const int k0 = kt * AN;
#pragma unroll
        for (int ni = 0; ni < 8; ni++) {
            int kc = k0 + ni * 8 + 2 * t;
            sacc[ni][0] = (kc     <= qr0) ? sacc[ni][0] * scale : -1e30f;
            sacc[ni][1] = (kc + 1 <= qr0) ? sacc[ni][1] * scale : -1e30f;
            sacc[ni][2] = (kc     <= qr1) ? sacc[ni][2] * scale : -1e30f;
            sacc[ni][3] = (kc + 1 <= qr1) ? sacc[ni][3] * scale : -1e30f;
        }

        float mx0 = -1e30f, mx1 = -1e30f;
#pragma unroll
        for (int ni = 0; ni < 8; ni++) {
            mx0 = fmaxf(mx0, fmaxf(sacc[ni][0], sacc[ni][1]));
            mx1 = fmaxf(mx1, fmaxf(sacc[ni][2], sacc[ni][3]));
        }
        mx0 = fmaxf(mx0, __shfl_xor_sync(0xffffffffu, mx0, 1));
        mx0 = fmaxf(mx0, __shfl_xor_sync(0xffffffffu, mx0, 2));
        mx1 = fmaxf(mx1, __shfl_xor_sync(0xffffffffu, mx1, 1));
        mx1 = fmaxf(mx1, __shfl_xor_sync(0xffffffffu, mx1, 2));
        float mn0 = fmaxf(m0, mx0), mn1 = fmaxf(m1, mx1);
        float s0 = 0.f, s1 = 0.f;
#pragma unroll
        for (int ni = 0; ni < 8; ni++) {
            sacc[ni][0] = __expf(sacc[ni][0] - mn0);
            sacc[ni][1] = __expf(sacc[ni][1] - mn0);
            sacc[ni][2] = __expf(sacc[ni][2] - mn1);
            sacc[ni][3] = __expf(sacc[ni][3] - mn1);
            s0 += sacc[ni][0] + sacc[ni][1];
            s1 += sacc[ni][2] + sacc[ni][3];
        }
        s0 += __shfl_xor_sync(0xffffffffu, s0, 1);
        s0 += __shfl_xor_sync(0xffffffffu, s0, 2);
        s1 += __shfl_xor_sync(0xffffffffu, s1, 1);
        s1 += __shfl_xor_sync(0xffffffffu, s1, 2);
        float r0f = __expf(m0 - mn0), r1f = __expf(m1 - mn1);
        l0 = l0 * r0f + s0; l1 = l1 * r1f + s1;
        m0 = mn0; m1 = mn1;

#pragma unroll
        for (int ni = 0; ni < 16; ni++) {
            o[ni][0] *= r0f; o[ni][1] *= r0f;
            o[ni][2] *= r1f; o[ni][3] *= r1f;
        }

#pragma unroll
        for (int ni = 0; ni < 8; ni++) {
            int col = ni * 8 + 2 * t;
            *(uint32_t*)&sP[(wm + g) * PH + col] = pack_h2(sacc[ni][0], sacc[ni][1]);
            *(uint32_t*)&sP[(wm + 8 + g) * PH + col] = pack_h2(sacc[ni][2], sacc[ni][3]);
        }
        __syncwarp();

#pragma unroll
        for (int kk = 0; kk < AN; kk += 16) {
            uint32_t ap[4];
            LDSM_X4(ap, pbase + p_lds + (uint32_t)(kk * 2));
#pragma unroll
            for (int ni2 = 0; ni2 < 8; ni2++) {
                int ncol = ni2 * 16 + ((lane >> 4) << 3);
                uint32_t vaddr = smem_u32(&sV[(kk + (lane & 15)) * QH + ncol]);
                uint32_t vb[4];
                asm volatile(
                    "ldmatrix.sync.aligned.m8n8.x4.trans.shared.b16 {%0,%1,%2,%3}, [%4];"
                    : "=r"(vb[0]), "=r"(vb[1]), "=r"(vb[2]), "=r"(vb[3]) : "r"(vaddr));
                MMA_F16(o[ni2 * 2], ap, vb);
                MMA_F16(o[ni2 * 2 + 1], ap, (vb + 2));
            }
        }
        __syncthreads();   // drain compute(kt) before next iter's loads reuse buffer
    }

    float invl0 = 1.0f / l0, invl1 = 1.0f / l1;
    size_t r0 = ((size_t)(b * T_ + q0 + wm + g) * H_ + h) * D_;
    size_t r1 = ((size_t)(b * T_ + q0 + wm + 8 + g) * H_ + h) * D_;
#pragma unroll
    for (int ni = 0; ni < 16; ni++) {
        int col = ni * 8 + 2 * t;
        *(uint32_t*)&out[r0 + col] = pack_h2(o[ni][0] * invl0, o[ni][1] * invl0);
        *(uint32_t*)&out[r1 + col] = pack_h2(o[ni][2] * invl1, o[ni][3] * invl1);
    }
}

// ---------------- launcher ----------------
extern "C" void kernel_launch(void* const* d_in, const int* in_sizes, int n_in,
                              void* d_out, int out_size) {
    const float* x = (const float*)d_in[0];
    const float* Wq = (const float*)d_in[3];
    const float* Wk = (const float*)d_in[4];
    const float* Wv = (const float*)d_in[5];
    const float* Wo = (const float*)d_in[6];
    float* out = (float*)d_out;

    __half *xh, *qkvh, *atth, *wth;
    float2* tab;
    cudaGetSymbolAddress((void**)&xh, g_xh);
    cudaGetSymbolAddress((void**)&qkvh, g_qkvh);
    cudaGetSymbolAddress((void**)&atth, g_atth);
    cudaGetSymbolAddress((void**)&wth, g_wth);
    cudaGetSymbolAddress((void**)&tab, g_tab);
    __half* wqkvT = wth;
    __half* woT = wth + 4096 * 2048;

    cudaFuncSetAttribute(attn_kernel, cudaFuncAttributeMaxDynamicSharedMemorySize,
                         ATTN_SMEM_BYTES);
    cudaFuncSetAttribute(gemm_h, cudaFuncAttributeMaxDynamicSharedMemorySize,
                         GEMM_SMEM_BYTES);

    const int M = B_ * T_;

    prep_all<<<16896, 256>>>(x, Wq, Wk, Wv, Wo, xh, wth, tab);

    gemm_h<<<dim3(4096 / 128, M / 128), 256, GEMM_SMEM_BYTES>>>(
        xh, wqkvT, qkvh, nullptr, M, 4096, C_, 1, 1, tab);
    attn_kernel<<<dim3(T_ / AM, H_, B_), 256, ATTN_SMEM_BYTES>>>(qkvh, atth);
    gemm_h<<<dim3(C_ / 128, M / 128), 256, GEMM_SMEM_BYTES>>>(
        atth, woT, nullptr, out, M, C_, C_, 0, 0, tab);
}

// round 17
// speedup vs baseline: 1.1339x; 1.1339x over previous
#include <cuda_runtime.h>
#include <cuda_fp16.h>
#include <math.h>
#include <stdint.h>

#define B_  2
#define T_  2048
#define C_  2048
#define H_  16
#define HK_ 8
#define D_  128
#define G_  2

// ---------------- scratch ----------------
__device__ __half g_xh[(size_t)B_ * T_ * C_];
__device__ __half g_qkvh[(size_t)B_ * T_ * 4096];
__device__ __half g_atth[(size_t)B_ * T_ * 2048];
__device__ __half g_wth[4096 * 2048 + 2048 * 2048];
__device__ float2 g_tab[T_ * 64];

// ---------------- helpers ----------------
__device__ __forceinline__ uint32_t smem_u32(const void* p) {
    uint32_t a;
    asm("{ .reg .u64 t; cvta.to.shared.u64 t, %1; cvt.u32.u64 %0, t; }" : "=r"(a) : "l"(p));
    return a;
}
__device__ __forceinline__ void cp_async16(uint32_t dst, const void* src) {
    asm volatile("cp.async.cg.shared.global [%0], [%1], 16;" :: "r"(dst), "l"(src));
}
#define CP_COMMIT() asm volatile("cp.async.commit_group;" ::: "memory")
#define CP_WAIT(n)  asm volatile("cp.async.wait_group %0;" :: "n"(n) : "memory")

#define MMA_F16(d, a, b)                                                       \
    asm volatile(                                                              \
        "mma.sync.aligned.m16n8k16.row.col.f32.f16.f16.f32 "                   \
        "{%0,%1,%2,%3}, {%4,%5,%6,%7}, {%8,%9}, {%0,%1,%2,%3};\n"              \
        : "+f"((d)[0]), "+f"((d)[1]), "+f"((d)[2]), "+f"((d)[3])               \
        : "r"((a)[0]), "r"((a)[1]), "r"((a)[2]), "r"((a)[3]),                  \
          "r"((b)[0]), "r"((b)[1]))

#define LDSM_X4(r, addr)                                                       \
    asm volatile("ldmatrix.sync.aligned.m8n8.x4.shared.b16 {%0,%1,%2,%3}, [%4];" \
        : "=r"((r)[0]), "=r"((r)[1]), "=r"((r)[2]), "=r"((r)[3]) : "r"(addr))

__device__ __forceinline__ uint32_t pack_h2(float a, float b) {
    __half2 h = __floats2half2_rn(a, b);
    return *(uint32_t*)&h;
}

// ---------------- fused prep kernel ----------------
__global__ __launch_bounds__(256)
void prep_all(const float* __restrict__ x, const float* __restrict__ Wq,
              const float* __restrict__ Wk, const float* __restrict__ Wv,
              const float* __restrict__ Wo, __half* __restrict__ xh,
              __half* __restrict__ wth, float2* __restrict__ tab) {
    int bid = blockIdx.x;
    if (bid < 12288) {
        __shared__ float tile[32][33];
        const float* W;
        __half* Wt;
        int N, lbid;
        if (bid < 4096)      { W = Wq; Wt = wth;               N = 2048; lbid = bid; }
        else if (bid < 6144) { W = Wk; Wt = wth + 2048 * 2048; N = 1024; lbid = bid - 4096; }
        else if (bid < 8192) { W = Wv; Wt = wth + 3072 * 2048; N = 1024; lbid = bid - 6144; }
        else                 { W = Wo; Wt = wth + 4096 * 2048; N = 2048; lbid = bid - 8192; }
        const int K = 2048;
        int tn = N / 32;
        int n0 = (lbid % tn) * 32, k0 = (lbid / tn) * 32;
        int tx = threadIdx.x & 31, ty = threadIdx.x >> 5;
#pragma unroll
        for (int j = 0; j < 32; j += 8)
            tile[ty + j][tx] = W[(size_t)(k0 + ty + j) * N + n0 + tx];
        __syncthreads();
#pragma unroll
        for (int j = 0; j < 32; j += 8)
            Wt[(size_t)(n0 + ty + j) * K + k0 + tx] = __float2half_rn(tile[tx][ty + j]);
    } else if (bid < 16384) {
        int i = (bid - 12288) * 256 + threadIdx.x;
        float4 v0 = ((const float4*)x)[i * 2];
        float4 v1 = ((const float4*)x)[i * 2 + 1];
        uint4 u;
        u.x = pack_h2(v0.x, v0.y); u.y = pack_h2(v0.z, v0.w);
        u.z = pack_h2(v1.x, v1.y); u.w = pack_h2(v1.z, v1.w);
        ((uint4*)xh)[i] = u;
    } else {
        int i = (bid - 16384) * 256 + threadIdx.x;
        int j = i & 63, t = i >> 6;
        float theta = powf(10000.0f, (float)(2 * j) * (1.0f / 128.0f));
        float freq = (float)t / theta;
        tab[i] = make_float2(cosf(freq), sinf(freq));
    }
}

// -------- 3-stage pipelined fp16 GEMM, 128x128 block, 64x32 warp tiles (R13) --
#define KCH 64
#define HSTR 72
#define STAGEH (2 * 128 * HSTR)
#define GEMM_SMEM_BYTES (3 * STAGEH * 2)

__global__ __launch_bounds__(256, 2)
void gemm_h(const __half* __restrict__ A, const __half* __restrict__ Bt,
            __half* __restrict__ Ch, float* __restrict__ Cf,
            int M, int N, int K, int do_rope, int out_half,
            const float2* __restrict__ tab) {
    extern __shared__ __align__(16) __half smh[];
    const uint32_t sbase = smem_u32(smh);

    const int tid = threadIdx.x;
    const int lane = tid & 31;
    const int wid = tid >> 5;
    const int g = lane >> 2, t = lane & 3;
    const int wm = (wid >> 2) * 64;
    const int wn = (wid & 3) * 32;
    const int m0 = blockIdx.y * 128, n0 = blockIdx.x * 128;

    const __half* Ab = A + (size_t)m0 * K;
    const __half* Bb = Bt + (size_t)n0 * K;

    float acc[4][4][4];
#pragma unroll
    for (int mi = 0; mi < 4; mi++)
#pragma unroll
        for (int ni = 0; ni < 4; ni++)
#pragma unroll
            for (int r = 0; r < 4; r++) acc[mi][ni][r] = 0.f;

    const int nchunk = K / KCH;
    const int r_ld = tid >> 3, c_ld = (tid & 7) * 8;
    const uint32_t ld_off = (uint32_t)((r_ld * HSTR + c_ld) * 2);

    const uint32_t a_lds = (uint32_t)(((wm + (lane & 15)) * HSTR + ((lane & 16) >> 1)) * 2);
    const uint32_t b_lds = (uint32_t)(((wn + (lane & 7) + ((lane & 16) >> 1)) * HSTR + (lane & 8)) * 2);

#pragma unroll
    for (int p = 0; p < 2; p++) {
        uint32_t sa = sbase + (uint32_t)(p * STAGEH * 2) + ld_off;
        const int k0 = p * KCH;
#pragma unroll
        for (int it = 0; it < 4; it++) {
            int r = r_ld + it * 32;
            uint32_t d = sa + (uint32_t)(it * 32 * HSTR * 2);
            cp_async16(d, Ab + (size_t)r * K + k0 + c_ld);
            cp_async16(d + 128 * HSTR * 2, Bb + (size_t)r * K + k0 + c_ld);
        }
        CP_COMMIT();
    }

    for (int c = 0; c < nchunk; c++) {
        if (c + 1 < nchunk) { CP_WAIT(1); } else { CP_WAIT(0); }
        __syncthreads();
        if (c + 2 < nchunk) {
            const int k0 = (c + 2) * KCH;
            uint32_t sa = sbase + (uint32_t)(((c + 2) % 3) * STAGEH * 2) + ld_off;
#pragma unroll
            for (int it = 0; it < 4; it++) {
                int r = r_ld + it * 32;
                uint32_t d = sa + (uint32_t)(it * 32 * HSTR * 2);
                cp_async16(d, Ab + (size_t)r * K + k0 + c_ld);
                cp_async16(d + 128 * HSTR * 2, Bb + (size_t)r * K + k0 + c_ld);
            }
            CP_COMMIT();
        }

        const uint32_t Abase = sbase + (uint32_t)((c % 3) * STAGEH * 2);
        const uint32_t Bbase = Abase + 128 * HSTR * 2;

#pragma unroll
        for (int kk = 0; kk < KCH; kk += 16) {
            uint32_t af[4][4], bf[2][4];
#pragma unroll
            for (int mi = 0; mi < 4; mi++)
                LDSM_X4(af[mi], Abase + a_lds + (uint32_t)((mi * 16 * HSTR + kk) * 2));
#pragma unroll
            for (int nb = 0; nb < 2; nb++)
                LDSM_X4(bf[nb], Bbase + b_lds + (uint32_t)((nb * 16 * HSTR + kk) * 2));
#pragma unroll
            for (int mi = 0; mi < 4; mi++)
#pragma unroll
                for (int ni = 0; ni < 4; ni++)
                    MMA_F16(acc[mi][ni], af[mi], (&bf[ni >> 1][(ni & 1) * 2]));
        }
    }
    __syncthreads();

    float* sC = (float*)smh;
#pragma unroll
    for (int mi = 0; mi < 4; mi++)
#pragma unroll
        for (int ni = 0; ni < 4; ni++) {
            int col = wn + ni * 8 + 2 * t;
            int r0 = wm + mi * 16 + g;
            *(float2*)&sC[r0 * 132 + col] = make_float2(acc[mi][ni][0], acc[mi][ni][1]);
            *(float2*)&sC[(r0 + 8) * 132 + col] = make_float2(acc[mi][ni][2], acc[mi][ni][3]);
        }
    __syncthreads();

    if (do_rope && n0 < 3072) {
#pragma unroll
        for (int it = 0; it < 32; it++) {
            int i = tid + it * 256;
            int r = i >> 6, j = i & 63;
            int tpos = (m0 + r) & (T_ - 1);
            float2 cs = tab[tpos * 64 + j];
            float x1 = sC[r * 132 + j];
            float x2 = sC[r * 132 + j + 64];
            sC[r * 132 + j]      = x1 * cs.x - x2 * cs.y;
            sC[r * 132 + j + 64] = x2 * cs.x + x1 * cs.y;
        }
        __syncthreads();
    }

    if (out_half) {
#pragma unroll
        for (int it = 0; it < 16; it++) {
            int i = tid + it * 256;
            int r = i >> 5, c4 = (i & 31) * 4;
            uint2 u = make_uint2(pack_h2(sC[r * 132 + c4], sC[r * 132 + c4 + 1]),
                                 pack_h2(sC[r * 132 + c4 + 2], sC[r * 132 + c4 + 3]));
            *(uint2*)&Ch[(size_t)(m0 + r) * N + n0 + c4] = u;
        }
    } else {
#pragma unroll
        for (int it = 0; it < 16; it++) {
            int i = tid + it * 256;
            int r = i >> 5, c4 = (i & 31) * 4;
            float4 v = make_float4(sC[r * 132 + c4], sC[r * 132 + c4 + 1],
                                   sC[r * 132 + c4 + 2], sC[r * 132 + c4 + 3]);
            *(float4*)&Cf[(size_t)(m0 + r) * N + n0 + c4] = v;
        }
    }
}

// ------- Flash attention: AN=128 k-tiles, 2-stage KV (2 syncs/tile), 1 CTA/SM --
#define AM 128
#define AN 128
#define QH 136
#define KVBUF (AN * QH)   // 17408 halfs per K (or V) buffer
#define ATTN_SMEM_BYTES ((AM * QH + 4 * KVBUF) * 2)   // 174080

__global__ __launch_bounds__(256, 1)
void attn_kernel(const __half* __restrict__ qkv, __half* __restrict__ out) {
    extern __shared__ __align__(16) __half sm[];
    __half* sQ = sm;                    // reused as sP after Q hoist
    __half* sKV = sQ + AM * QH;
    __half* sP = sQ;
    const uint32_t kvbase = smem_u32(sKV);
    const uint32_t qbase = smem_u32(sQ);
    const uint32_t pbase = qbase;

    const int tid = threadIdx.x;
    const int lane = tid & 31;
    const int wid = tid >> 5;
    const int g = lane >> 2, t = lane & 3;
    const int qt = (gridDim.x - 1) - blockIdx.x;
    const int h = blockIdx.y, b = blockIdx.z;
    const int kh = h / G_;
    const int q0 = qt * AM;
    const int wm = wid * 16;
    const float scale = 0.08838834764831845f;

    const int qoff = h * D_;
    const int koff = 2048 + kh * D_;
    const int voff = 3072 + kh * D_;

    const uint32_t q_lds = (uint32_t)(((wm + (lane & 15)) * QH + ((lane & 16) >> 1)) * 2);
    const uint32_t k_lds = (uint32_t)((((lane & 7) + ((lane & 16) >> 1)) * QH + (lane & 8)) * 2);
    const uint32_t p_lds = q_lds;   // sP aliases sQ, same stride/layout

    // stage Q -> smem (128 rows x 16 uint4 segs) -> register fragments
#pragma unroll
    for (int it = 0; it < 8; it++) {
        int i = tid + it * 256;          // 2048 segs
        int r = i >> 4, c8 = (i & 15) * 8;
        *(uint4*)&sQ[r * QH + c8] =
            *(const uint4*)&qkv[(size_t)(b * T_ + q0 + r) * 4096 + qoff + c8];
    }
    __syncthreads();
    uint32_t qf[8][4];
#pragma unroll
    for (int kk8 = 0; kk8 < 8; kk8++)
        LDSM_X4(qf[kk8], qbase + q_lds + (uint32_t)(kk8 * 16 * 2));
    __syncthreads();

    float m0 = -1e30f, m1 = -1e30f, l0 = 0.f, l1 = 0.f;
    float o[16][4];
#pragma unroll
    for (int ni = 0; ni < 16; ni++)
#pragma unroll
        for (int r = 0; r < 4; r++) o[ni][r] = 0.f;

    const int qr0 = q0 + wm + g, qr1 = qr0 + 8;
    const int ntiles = qt + 1;

    // prologue: tile 0 (K 2048 segs + V 2048 segs = 16 iters)
    {
#pragma unroll
        for (int it = 0; it < 16; it++) {
            int i = tid + it * 256;
            int j = i & 2047;
            int r = j >> 4, c8 = (j & 15) * 8;
            size_t rowb = (size_t)(b * T_ + r) * 4096;
            uint32_t d = kvbase + (uint32_t)((r * QH + c8) * 2);
            if (i < 2048) cp_async16(d, &qkv[rowb + koff + c8]);
            else          cp_async16(d + KVBUF * 2, &qkv[rowb + voff + c8]);
        }
        CP_COMMIT();
    }

    for (int kt = 0; kt < ntiles; kt++) {
        if (kt + 1 < ntiles) {
            const int k0n = (kt + 1) * AN;
            uint32_t base = kvbase + (uint32_t)(((kt + 1) & 1) * 2 * KVBUF * 2);
#pragma unroll
            for (int it = 0; it < 16; it++) {
                int i = tid + it * 256;
                int j = i & 2047;
                int r = j >> 4, c8 = (j & 15) * 8;
                size_t rowb = (size_t)(b * T_ + k0n + r) * 4096;
                uint32_t d = base + (uint32_t)((r * QH + c8) * 2);
                if (i < 2048) cp_async16(d, &qkv[rowb + koff + c8]);
                else          cp_async16(d + KVBUF * 2, &qkv[rowb + voff + c8]);
            }
            CP_COMMIT();
            CP_WAIT(1);
        } else {
            CP_WAIT(0);
        }
        __syncthreads();

        const uint32_t Kb = kvbase + (uint32_t)((kt & 1) * 2 * KVBUF * 2);
        const __half* sV = sKV + (kt & 1) * 2 * KVBUF + KVBUF;

        // ---- S = Q K^T (warp: 16 x 128) ----
        float sacc[16][4];
#pragma unroll
        for (int ni = 0; ni < 16; ni++)
#pragma unroll
            for (int r = 0; r < 4; r++) sacc[ni][r] = 0.f;

#pragma unroll
        for (int kk8 = 0; kk8 < 8; kk8++) {
#pragma unroll
            for (int nb = 0; nb < 8; nb++) {
                uint32_t kf[4];
                LDSM_X4(kf, Kb + k_lds + (uint32_t)((nb * 16 * QH + kk8 * 16) * 2));
                MMA_F16(sacc[nb * 2], qf[kk8], kf);
                MMA_F16(sacc[nb * 2 + 1], qf[kk8], (kf + 2));
            }
        }

        const int k0 = kt * AN;
#pragma unroll
        for (int ni = 0; ni < 16; ni++) {
            int kc = k0 + ni * 8 + 2 * t;
            sacc[ni][0] = (kc     <= qr0) ? sacc[ni][0] * scale : -1e30f;
            sacc[ni][1] = (kc + 1 <= qr0) ? sacc[ni][1] * scale : -1e30f;
            sacc[ni][2] = (kc     <= qr1) ? sacc[ni][2] * scale : -1e30f;
            sacc[ni][3] = (kc + 1 <= qr1) ? sacc[ni][3] * scale : -1e30f;
        }

        // ---- register online softmax ----
        float mx0 = -1e30f, mx1 = -1e30f;
#pragma unroll
        for (int ni = 0; ni < 16; ni++) {
            mx0 = fmaxf(mx0, fmaxf(sacc[ni][0], sacc[ni][1]));
            mx1 = fmaxf(mx1, fmaxf(sacc[ni][2], sacc[ni][3]));
        }
        mx0 = fmaxf(mx0, __shfl_xor_sync(0xffffffffu, mx0, 1));
        mx0 = fmaxf(mx0, __shfl_xor_sync(0xffffffffu, mx0, 2));
        mx1 = fmaxf(mx1, __shfl_xor_sync(0xffffffffu, mx1, 1));
        mx1 = fmaxf(mx1, __shfl_xor_sync(0xffffffffu, mx1, 2));
        float mn0 = fmaxf(m0, mx0), mn1 = fmaxf(m1, mx1);
        float s0 = 0.f, s1 = 0.f;
#pragma unroll
        for (int ni = 0; ni < 16; ni++) {
            sacc[ni][0] = __expf(sacc[ni][0] - mn0);
            sacc[ni][1] = __expf(sacc[ni][1] - mn0);
            sacc[ni][2] = __expf(sacc[ni][2] - mn1);
            sacc[ni][3] = __expf(sacc[ni][3] - mn1);
            s0 += sacc[ni][0] + sacc[ni][1];
            s1 += sacc[ni][2] + sacc[ni][3];
        }
        s0 += __shfl_xor_sync(0xffffffffu, s0, 1);
        s0 += __shfl_xor_sync(0xffffffffu, s0, 2);
        s1 += __shfl_xor_sync(0xffffffffu, s1, 1);
        s1 += __shfl_xor_sync(0xffffffffu, s1, 2);
        float r0f = __expf(m0 - mn0), r1f = __expf(m1 - mn1);
        l0 = l0 * r0f + s0; l1 = l1 * r1f + s1;
        m0 = mn0; m1 = mn1;

#pragma unroll
        for (int ni = 0; ni < 16; ni++) {
            o[ni][0] *= r0f; o[ni][1] *= r0f;
            o[ni][2] *= r1f; o[ni][3] *= r1f;
        }

        // P -> warp-private smem patch (half2), 128 cols, stride QH
#pragma unroll
        for (int ni = 0; ni < 16; ni++) {
            int col = ni * 8 + 2 * t;
            *(uint32_t*)&sP[(wm + g) * QH + col] = pack_h2(sacc[ni][0], sacc[ni][1]);
            *(uint32_t*)&sP[(wm + 8 + g) * QH + col] = pack_h2(sacc[ni][2], sacc[ni][3]);
        }
        __syncwarp();

        // ---- O += P V (warp: 16 x 128, K-depth 128) ----
#pragma unroll
        for (int kk = 0; kk < AN; kk += 16) {
            uint32_t ap[4];
            LDSM_X4(ap, pbase + p_lds + (uint32_t)(kk * 2));
#pragma unroll
            for (int ni2 = 0; ni2 < 8; ni2++) {
                int ncol = ni2 * 16 + ((lane >> 4) << 3);
                uint32_t vaddr = smem_u32(&sV[(kk + (lane & 15)) * QH + ncol]);
                uint32_t vb[4];
                asm volatile(
                    "ldmatrix.sync.aligned.m8n8.x4.trans.shared.b16 {%0,%1,%2,%3}, [%4];"
                    : "=r"(vb[0]), "=r"(vb[1]), "=r"(vb[2]), "=r"(vb[3]) : "r"(vaddr));
                MMA_F16(o[ni2 * 2], ap, vb);
                MMA_F16(o[ni2 * 2 + 1], ap, (vb + 2));
            }
        }
        __syncthreads();   // drain compute(kt) before next iter reuses buffer
    }

    float invl0 = 1.0f / l0, invl1 = 1.0f / l1;
    size_t r0 = ((size_t)(b * T_ + q0 + wm + g) * H_ + h) * D_;
    size_t r1 = ((size_t)(b * T_ + q0 + wm + 8 + g) * H_ + h) * D_;
#pragma unroll
    for (int ni = 0; ni < 16; ni++) {
        int col = ni * 8 + 2 * t;
        *(uint32_t*)&out[r0 + col] = pack_h2(o[ni][0] * invl0, o[ni][1] * invl0);
        *(uint32_t*)&out[r1 + col] = pack_h2(o[ni][2] * invl1, o[ni][3] * invl1);
    }
}

// ---------------- launcher ----------------
extern "C" void kernel_launch(void* const* d_in, const int* in_sizes, int n_in,
                              void* d_out, int out_size) {
    const float* x = (const float*)d_in[0];
    const float* Wq = (const float*)d_in[3];
    const float* Wk = (const float*)d_in[4];
    const float* Wv = (const float*)d_in[5];
    const float* Wo = (const float*)d_in[6];
    float* out = (float*)d_out;

    __half *xh, *qkvh, *atth, *wth;
    float2* tab;
    cudaGetSymbolAddress((void**)&xh, g_xh);
    cudaGetSymbolAddress((void**)&qkvh, g_qkvh);
    cudaGetSymbolAddress((void**)&atth, g_atth);
    cudaGetSymbolAddress((void**)&wth, g_wth);
    cudaGetSymbolAddress((void**)&tab, g_tab);
    __half* wqkvT = wth;
    __half* woT = wth + 4096 * 2048;

    cudaFuncSetAttribute(attn_kernel, cudaFuncAttributeMaxDynamicSharedMemorySize,
                         ATTN_SMEM_BYTES);
    cudaFuncSetAttribute(gemm_h, cudaFuncAttributeMaxDynamicSharedMemorySize,
                         GEMM_SMEM_BYTES);

    const int M = B_ * T_;

    prep_all<<<16896, 256>>>(x, Wq, Wk, Wv, Wo, xh, wth, tab);

    gemm_h<<<dim3(4096 / 128, M / 128), 256, GEMM_SMEM_BYTES>>>(
        xh, wqkvT, qkvh, nullptr, M, 4096, C_, 1, 1, tab);
    attn_kernel<<<dim3(T_ / AM, H_, B_), 256, ATTN_SMEM_BYTES>>>(qkvh, atth);
    gemm_h<<<dim3(C_ / 128, M / 128), 256, GEMM_SMEM_BYTES>>>(
        atth, woT, nullptr, out, M, C_, C_, 0, 0, tab);
}